// round 8
// baseline (speedup 1.0000x reference)
#include <cuda_runtime.h>
#include <cuda_fp16.h>

#define Cc 10
#define Bb 512
#define Nn 1152
#define Ii 8
#define Oo 16

// Scratch u_hat[C,B,N,O] in fp16, stored as uint4 (8 halves per uint4) = 189 MB
__device__ uint4 g_uhat[(size_t)Cc * Bb * Nn * Oo / 8];

typedef unsigned long long u64;

// ---- packed f32x2 helpers (ptxas never auto-fuses these from C++) ----
__device__ __forceinline__ u64 fma2(u64 a, u64 b, u64 c) {
    u64 d; asm("fma.rn.f32x2 %0, %1, %2, %3;" : "=l"(d) : "l"(a), "l"(b), "l"(c)); return d;
}
__device__ __forceinline__ u64 mul2(u64 a, u64 b) {
    u64 d; asm("mul.rn.f32x2 %0, %1, %2;" : "=l"(d) : "l"(a), "l"(b)); return d;
}
__device__ __forceinline__ u64 add2(u64 a, u64 b) {
    u64 d; asm("add.rn.f32x2 %0, %1, %2;" : "=l"(d) : "l"(a), "l"(b)); return d;
}
__device__ __forceinline__ u64 dup2(float x) {
    u64 d; asm("mov.b64 %0, {%1, %1};" : "=l"(d) : "f"(x)); return d;
}
__device__ __forceinline__ u64 pack2(float lo, float hi) {
    u64 d; asm("mov.b64 %0, {%1, %2};" : "=l"(d) : "f"(lo), "f"(hi)); return d;
}
__device__ __forceinline__ void unpack2(u64 a, float& lo, float& hi) {
    asm("mov.b64 {%0, %1}, %2;" : "=f"(lo), "=f"(hi) : "l"(a));
}
// pack two f32 into one f16x2 word (lo -> lower half, hi -> upper half)
__device__ __forceinline__ unsigned cvth2(float lo, float hi) {
    __half2 h = __floats2half2_rn(lo, hi);
    return *(unsigned*)&h;
}
// f16x2 word -> packed f32x2 (lower half -> lo f32, upper half -> hi f32)
__device__ __forceinline__ u64 h2f2(unsigned w) {
    __half2 h = *(__half2*)&w;
    float2 f = __half22float2(h);
    return pack2(f.x, f.y);
}

// ---------------------------------------------------------------------------
// Phase 1: u_hat[c,b,n,o] = sum_i u[b,n,i] * W[c,n,i,o], stored fp16.
// 256 thr = 128 n x 2 o-halves. W[c,n,:,8h..8h+7] in 64 regs; 128-batch loop
// (b-block 128 halves W L2 re-read traffic vs 64 -- phase1 is LTS-cap bound).
// Grid: (N/128 = 9, B/128 = 4, C = 10) = 360 CTAs, no smem.
// ---------------------------------------------------------------------------
__global__ __launch_bounds__(256) void uhat_kernel(const float* __restrict__ u,
                                                   const float* __restrict__ W) {
    const int tid = threadIdx.x;
    const int n   = blockIdx.x * 128 + (tid >> 1);
    const int h   = tid & 1;
    const int b0  = blockIdx.y * 128;
    const int c   = blockIdx.z;

    // W[c,n,i, 8h..8h+7] as packed f32 pairs
    u64 w2[8][4];
    const float* wc = W + (((size_t)c * Nn + n) * Ii) * Oo + h * 8;
#pragma unroll
    for (int i = 0; i < 8; i++) {
        ulonglong2 aa = *(const ulonglong2*)(wc + i * Oo);
        ulonglong2 bb = *(const ulonglong2*)(wc + i * Oo + 4);
        w2[i][0] = aa.x; w2[i][1] = aa.y; w2[i][2] = bb.x; w2[i][3] = bb.y;
    }

    const float* ub = u + ((size_t)b0 * Nn + n) * Ii;
    uint4* ob = g_uhat + (((size_t)c * Bb + b0) * Nn + n) * 2 + h;

#pragma unroll 4
    for (int j = 0; j < 128; j++) {
        const float4* up = (const float4*)(ub + (size_t)j * (Nn * Ii));
        float4 a = __ldg(up);
        float4 b = __ldg(up + 1);
        float usv[8] = {a.x, a.y, a.z, a.w, b.x, b.y, b.z, b.w};

        u64 acc[4];
        {
            u64 ud = dup2(usv[0]);
#pragma unroll
            for (int k = 0; k < 4; k++) acc[k] = mul2(ud, w2[0][k]);
        }
#pragma unroll
        for (int i = 1; i < 8; i++) {
            u64 ud = dup2(usv[i]);
#pragma unroll
            for (int k = 0; k < 4; k++) acc[k] = fma2(ud, w2[i][k], acc[k]);
        }
        float r[8];
#pragma unroll
        for (int k = 0; k < 4; k++) unpack2(acc[k], r[2 * k], r[2 * k + 1]);

        uint4 st;
        st.x = cvth2(r[0], r[1]);
        st.y = cvth2(r[2], r[3]);
        st.z = cvth2(r[4], r[5]);
        st.w = cvth2(r[6], r[7]);
        __stcs(ob + (size_t)j * (Nn * 2), st);
    }
}

// ---------------------------------------------------------------------------
// Phase 2: routing. 256-thr CTA per (c,b); thread = (n-lane 0..127, o-half).
// Slab held COMPRESSED in regs: 9 x uint4 of f16x2 (36 data regs vs 72),
// converted h2 -> packed f32x2 on the fly in each pass (each converted row is
// used twice immediately: logit dot + weighted sum). f32 math order unchanged.
// launch_bounds(256,3): 24 warps/SM so slab loads overlap compute.
// Grid: (B, C), reverse walk to catch phase-1's L2-resident tail.
// ---------------------------------------------------------------------------
__global__ __launch_bounds__(256, 3) void routing_kernel(float* __restrict__ out) {
    const int tid  = threadIdx.x;
    const int b    = (Bb - 1) - blockIdx.x;
    const int c    = (Cc - 1) - blockIdx.y;
    const int lane = tid & 31, wid = tid >> 5;
    const int nl   = tid >> 1, h = tid & 1;

    __shared__ float red[8][2][12];  // [warp][half][S0..7, z]
    __shared__ float Vs[16];         // accumulated v

    // Load slab raw: one uint4 (8 fp16) per row per thread, fully coalesced.
    uint4 uh[9];
    const uint4* p = g_uhat + ((size_t)c * Bb + b) * (size_t)(Nn * 2);
#pragma unroll
    for (int r = 0; r < 9; r++) uh[r] = __ldcs(p + (size_t)(r * 128 + nl) * 2 + h);

    for (int it = 0; it < 3; it++) {
        float S[8], z;
        u64 S2[4] = {0ull, 0ull, 0ull, 0ull};
        if (it == 0) {
#pragma unroll
            for (int r = 0; r < 9; r++) {
                S2[0] = add2(S2[0], h2f2(uh[r].x));
                S2[1] = add2(S2[1], h2f2(uh[r].y));
                S2[2] = add2(S2[2], h2f2(uh[r].z));
                S2[3] = add2(S2[3], h2f2(uh[r].w));
            }
            z = 9.0f;  // 9 rows, unit weight
        } else {
            u64 V2[4];
#pragma unroll
            for (int k = 0; k < 4; k++)
                V2[k] = pack2(Vs[8 * h + 2 * k], Vs[8 * h + 2 * k + 1]);
            z = 0.0f;
#pragma unroll
            for (int r = 0; r < 9; r++) {
                u64 f0 = h2f2(uh[r].x), f1 = h2f2(uh[r].y);
                u64 f2 = h2f2(uh[r].z), f3 = h2f2(uh[r].w);
                u64 d = mul2(f0, V2[0]);
                d = fma2(f1, V2[1], d);
                d = fma2(f2, V2[2], d);
                d = fma2(f3, V2[3], d);
                float lo, hi; unpack2(d, lo, hi);
                float a = lo + hi;
                a += __shfl_xor_sync(0xffffffffu, a, 1);  // partner o-half
                float e = __expf(a);
                z += e;
                u64 ed = dup2(e);
                S2[0] = fma2(ed, f0, S2[0]);
                S2[1] = fma2(ed, f1, S2[1]);
                S2[2] = fma2(ed, f2, S2[2]);
                S2[3] = fma2(ed, f3, S2[3]);
            }
        }
#pragma unroll
        for (int k = 0; k < 4; k++) unpack2(S2[k], S[2 * k], S[2 * k + 1]);

        // Reduce over the 16 same-half lanes of each warp (xor 2,4,8,16)
#pragma unroll
        for (int off = 2; off <= 16; off <<= 1) {
            z += __shfl_xor_sync(0xffffffffu, z, off);
#pragma unroll
            for (int o = 0; o < 8; o++)
                S[o] += __shfl_xor_sync(0xffffffffu, S[o], off);
        }
        if (lane < 2) {  // lane 0 = half 0, lane 1 = half 1
#pragma unroll
            for (int o = 0; o < 8; o++) red[wid][lane][o] = S[o];
            red[wid][lane][8] = z;
        }
        __syncthreads();

        // Final combine + squash: 16 threads, one per o
        if (tid < 16) {
            int o = tid, hh = o >> 3, k = o & 7;
            float s = 0.0f, Z = 0.0f;
#pragma unroll
            for (int w = 0; w < 8; w++) { s += red[w][hh][k]; Z += red[w][0][8]; }
            s /= Z;
            float sn = s * s;
#pragma unroll
            for (int off = 1; off <= 8; off <<= 1)
                sn += __shfl_xor_sync(0xffffu, sn, off);
            float fq = (sn / (1.0f + sn)) * rsqrtf(sn);
            float v = s * fq;
            if (it == 2) out[((size_t)c * Bb + b) * Oo + o] = v;
            else Vs[o] = (it == 0) ? v : (Vs[o] + v);
        }
        __syncthreads();
    }
}

// ---------------------------------------------------------------------------
extern "C" void kernel_launch(void* const* d_in, const int* in_sizes, int n_in,
                              void* d_out, int out_size) {
    const float* u = (const float*)d_in[0];  // [B,N,I]
    const float* W = (const float*)d_in[1];  // [C,N,I,O]
    float* out = (float*)d_out;              // [C,B,1,1,O]

    uhat_kernel<<<dim3(Nn / 128, Bb / 128, Cc), 256>>>(u, W);
    routing_kernel<<<dim3(Bb, Cc), 256>>>(out);
}

// round 9
// speedup vs baseline: 1.0628x; 1.0628x over previous
#include <cuda_runtime.h>
#include <cuda_fp16.h>

#define Cc 10
#define Bb 512
#define Nn 1152
#define Ii 8
#define Oo 16

// Scratch u_hat[C,B,N,O] in fp16, stored as uint4 (8 halves per uint4) = 189 MB
__device__ uint4 g_uhat[(size_t)Cc * Bb * Nn * Oo / 8];

typedef unsigned long long u64;

// ---- packed f32x2 helpers (ptxas never auto-fuses these from C++) ----
__device__ __forceinline__ u64 fma2(u64 a, u64 b, u64 c) {
    u64 d; asm("fma.rn.f32x2 %0, %1, %2, %3;" : "=l"(d) : "l"(a), "l"(b), "l"(c)); return d;
}
__device__ __forceinline__ u64 mul2(u64 a, u64 b) {
    u64 d; asm("mul.rn.f32x2 %0, %1, %2;" : "=l"(d) : "l"(a), "l"(b)); return d;
}
__device__ __forceinline__ u64 add2(u64 a, u64 b) {
    u64 d; asm("add.rn.f32x2 %0, %1, %2;" : "=l"(d) : "l"(a), "l"(b)); return d;
}
__device__ __forceinline__ u64 dup2(float x) {
    u64 d; asm("mov.b64 %0, {%1, %1};" : "=l"(d) : "f"(x)); return d;
}
__device__ __forceinline__ u64 pack2(float lo, float hi) {
    u64 d; asm("mov.b64 %0, {%1, %2};" : "=l"(d) : "f"(lo), "f"(hi)); return d;
}
__device__ __forceinline__ void unpack2(u64 a, float& lo, float& hi) {
    asm("mov.b64 {%0, %1}, %2;" : "=f"(lo), "=f"(hi) : "l"(a));
}
// pack two f32 into one f16x2 word (lo -> lower half, hi -> upper half)
__device__ __forceinline__ unsigned cvth2(float lo, float hi) {
    __half2 h = __floats2half2_rn(lo, hi);
    return *(unsigned*)&h;
}
// f16x2 word -> packed f32x2 (lower half -> lo f32, upper half -> hi f32)
__device__ __forceinline__ u64 h2f2(unsigned w) {
    __half2 h = *(__half2*)&w;
    float2 f = __half22float2(h);
    return pack2(f.x, f.y);
}

// ---------------------------------------------------------------------------
// Phase 1: u_hat[c,b,n,o] = sum_i u[b,n,i] * W[c,n,i,o], stored fp16.
// 256 thr = 128 n x 2 o-halves. W[c,n,:,8h..8h+7] in 64 regs; 64-batch loop.
// Grid: (N/128 = 9, B/64 = 8, C = 10) = 720 CTAs -- TLP (not LTS) limited,
// so keep the grid large (R8's 128-batch/360-CTA variant regressed).
// ---------------------------------------------------------------------------
__global__ __launch_bounds__(256) void uhat_kernel(const float* __restrict__ u,
                                                   const float* __restrict__ W) {
    const int tid = threadIdx.x;
    const int n   = blockIdx.x * 128 + (tid >> 1);
    const int h   = tid & 1;
    const int b0  = blockIdx.y * 64;
    const int c   = blockIdx.z;

    // W[c,n,i, 8h..8h+7] as packed f32 pairs
    u64 w2[8][4];
    const float* wc = W + (((size_t)c * Nn + n) * Ii) * Oo + h * 8;
#pragma unroll
    for (int i = 0; i < 8; i++) {
        ulonglong2 aa = *(const ulonglong2*)(wc + i * Oo);
        ulonglong2 bb = *(const ulonglong2*)(wc + i * Oo + 4);
        w2[i][0] = aa.x; w2[i][1] = aa.y; w2[i][2] = bb.x; w2[i][3] = bb.y;
    }

    const float* ub = u + ((size_t)b0 * Nn + n) * Ii;
    uint4* ob = g_uhat + (((size_t)c * Bb + b0) * Nn + n) * 2 + h;

#pragma unroll 4
    for (int j = 0; j < 64; j++) {
        const float4* up = (const float4*)(ub + (size_t)j * (Nn * Ii));
        float4 a = __ldg(up);
        float4 b = __ldg(up + 1);
        float usv[8] = {a.x, a.y, a.z, a.w, b.x, b.y, b.z, b.w};

        u64 acc[4];
        {
            u64 ud = dup2(usv[0]);
#pragma unroll
            for (int k = 0; k < 4; k++) acc[k] = mul2(ud, w2[0][k]);
        }
#pragma unroll
        for (int i = 1; i < 8; i++) {
            u64 ud = dup2(usv[i]);
#pragma unroll
            for (int k = 0; k < 4; k++) acc[k] = fma2(ud, w2[i][k], acc[k]);
        }
        float r[8];
#pragma unroll
        for (int k = 0; k < 4; k++) unpack2(acc[k], r[2 * k], r[2 * k + 1]);

        uint4 st;
        st.x = cvth2(r[0], r[1]);
        st.y = cvth2(r[2], r[3]);
        st.z = cvth2(r[4], r[5]);
        st.w = cvth2(r[6], r[7]);
        __stcs(ob + (size_t)j * (Nn * 2), st);
    }
}

// ---------------------------------------------------------------------------
// Phase 2: routing. 256-thr CTA per (c,b); thread = (n-lane 0..127, o-half).
// Slab pre-converted to f32x2 regs (R6 structure -- on-the-fly cvt regressed).
// Critical-path cuts vs R6:
//   - 1 barrier/iter (double-buffered red[] by parity; WAR separated by the
//     next iteration's barrier)
//   - redundant combine: ALL threads read the 8-warp partials (smem
//     broadcasts) and compute s/squash/V into registers Vr -- no tid<16
//     serial section, no Vs round-trip, no second barrier
//   - it0's softmax Z is exactly N=1152 (constant): no z reduce
// Grid: (B, C), reverse walk to catch phase-1's L2-resident tail.
// ---------------------------------------------------------------------------
__global__ __launch_bounds__(256, 2) void routing_kernel(float* __restrict__ out) {
    const int tid  = threadIdx.x;
    const int b    = (Bb - 1) - blockIdx.x;
    const int c    = (Cc - 1) - blockIdx.y;
    const int lane = tid & 31, wid = tid >> 5;
    const int nl   = tid >> 1, h = tid & 1;

    __shared__ float red[2][8][2][9];  // [parity][warp][half][S0..7, z]

    // Load slab: one uint4 (8 fp16) per row per thread; convert once to f32x2.
    u64 uh[9][4];
    const uint4* p = g_uhat + ((size_t)c * Bb + b) * (size_t)(Nn * 2);
#pragma unroll
    for (int r = 0; r < 9; r++) {
        uint4 t = __ldcs(p + (size_t)(r * 128 + nl) * 2 + h);
        uh[r][0] = h2f2(t.x);
        uh[r][1] = h2f2(t.y);
        uh[r][2] = h2f2(t.z);
        uh[r][3] = h2f2(t.w);
    }

    float Vr[8];  // accumulated v for this thread's o-half (regs, no smem)

    for (int it = 0; it < 3; it++) {
        const int pr = it & 1;
        float S[8], z = 0.0f;
        u64 S2[4] = {0ull, 0ull, 0ull, 0ull};
        if (it == 0) {
#pragma unroll
            for (int r = 0; r < 9; r++)
#pragma unroll
                for (int k = 0; k < 4; k++) S2[k] = add2(S2[k], uh[r][k]);
        } else {
            u64 V2[4];
#pragma unroll
            for (int k = 0; k < 4; k++) V2[k] = pack2(Vr[2 * k], Vr[2 * k + 1]);
#pragma unroll
            for (int r = 0; r < 9; r++) {
                u64 d = mul2(uh[r][0], V2[0]);
                d = fma2(uh[r][1], V2[1], d);
                d = fma2(uh[r][2], V2[2], d);
                d = fma2(uh[r][3], V2[3], d);
                float lo, hi; unpack2(d, lo, hi);
                float a = lo + hi;
                a += __shfl_xor_sync(0xffffffffu, a, 1);  // partner o-half
                float e = __expf(a);
                z += e;
                u64 ed = dup2(e);
#pragma unroll
                for (int k = 0; k < 4; k++) S2[k] = fma2(ed, uh[r][k], S2[k]);
            }
        }
#pragma unroll
        for (int k = 0; k < 4; k++) unpack2(S2[k], S[2 * k], S[2 * k + 1]);

        // Reduce over the 16 same-half lanes of each warp (xor 2,4,8,16)
#pragma unroll
        for (int off = 2; off <= 16; off <<= 1) {
            if (it > 0) z += __shfl_xor_sync(0xffffffffu, z, off);
#pragma unroll
            for (int o = 0; o < 8; o++)
                S[o] += __shfl_xor_sync(0xffffffffu, S[o], off);
        }
        if (lane < 2) {  // lane 0 = half 0, lane 1 = half 1
#pragma unroll
            for (int o = 0; o < 8; o++) red[pr][wid][lane][o] = S[o];
            red[pr][wid][lane][8] = z;
        }
        __syncthreads();

        // Redundant combine in every thread (smem broadcasts, conflict-free)
        float Z, s[8];
        if (it == 0) {
            Z = (float)Nn;  // softmax of zeros: Z is exactly N
        } else {
            Z = 0.0f;
#pragma unroll
            for (int w = 0; w < 8; w++) Z += red[pr][w][0][8];
        }
        float inv = 1.0f / Z;
        float snh = 0.0f;
#pragma unroll
        for (int k = 0; k < 8; k++) {
            float acc = 0.0f;
#pragma unroll
            for (int w = 0; w < 8; w++) acc += red[pr][w][h][k];
            s[k] = acc * inv;
            snh = fmaf(s[k], s[k], snh);
        }
        float sn = snh + __shfl_xor_sync(0xffffffffu, snh, 1);
        float fq = (sn / (1.0f + sn)) * rsqrtf(sn);
        if (it == 2) {
            if (tid < 2) {
                float* op = out + ((size_t)c * Bb + b) * Oo + h * 8;
#pragma unroll
                for (int k = 0; k < 8; k++) op[k] = s[k] * fq;
            }
        } else {
#pragma unroll
            for (int k = 0; k < 8; k++) {
                float v = s[k] * fq;
                Vr[k] = (it == 0) ? v : (Vr[k] + v);
            }
        }
    }
}

// ---------------------------------------------------------------------------
extern "C" void kernel_launch(void* const* d_in, const int* in_sizes, int n_in,
                              void* d_out, int out_size) {
    const float* u = (const float*)d_in[0];  // [B,N,I]
    const float* W = (const float*)d_in[1];  // [C,N,I,O]
    float* out = (float*)d_out;              // [C,B,1,1,O]

    uhat_kernel<<<dim3(Nn / 128, Bb / 64, Cc), 256>>>(u, W);
    routing_kernel<<<dim3(Bb, Cc), 256>>>(out);
}